// round 13
// baseline (speedup 1.0000x reference)
#include <cuda_runtime.h>
#include <math.h>
#include <stdint.h>

// Problem constants
#define BB   8
#define DD   64
#define NN   2048
#define KK   20
#define CC   128
#define O1   256
#define J1   10
#define T1   11
#define O2C  256
#define SS   40
#define GN   4
#define G1   4
#define G2P  16
#define NCH  4
#define RPAD 18
#define NB1  (BB * NN / G1)
#define NB2  (BB * NN / G2P)
#define C2HP (32 * KK)
#define C2ED (16 * KK)

typedef unsigned long long ull;

__device__ __forceinline__ ull fma2(ull a, ull b, ull c) {
    ull d;
    asm("fma.rn.f32x2 %0, %1, %2, %3;" : "=l"(d) : "l"(a), "l"(b), "l"(c));
    return d;
}
__device__ __forceinline__ ull dup2(float v) {
    ull d; unsigned int u = __float_as_uint(v);
    asm("mov.b64 %0, {%1, %1};" : "=l"(d) : "r"(u));
    return d;
}
__device__ __forceinline__ float2 unpk(ull v) {
    float2 r;
    asm("mov.b64 {%0, %1}, %2;" : "=f"(r.x), "=f"(r.y) : "l"(v));
    return r;
}

// ---------------- scratch ----------------
__device__ float g_sq[BB * NN];
__device__ int   g_idx[BB * NN * KK];
__device__ float g_ed[(size_t)BB * NN * 64 * KK];
__device__ float g_h [(size_t)BB * NN * J1 * O1];   // [b][n][j][o]
__device__ float g_bn1a[O1];
__device__ float g_bn1b[O1];
__device__ float g_y [BB * NN * O2C];
__device__ float g_bn2a[O2C];
__device__ float g_bn2b[O2C];
__device__ float g_w1t[64 * T1 * O1];               // [c][t][o]  (o-coalesced!)
__device__ float g_w1a[64 * O1];
__device__ float g_w2t[64 * KK * O2C];
__device__ float g_w2c[CC * KK * O2C];
__device__ float g_w2a[64 * O2C];
__device__ float g_p1[NB1 * O1];
__device__ float g_p2[NB1 * O1];
__device__ float g_q1[NB2 * O2C];
__device__ float g_q2[NB2 * O2C];

// ---------------- weight preprocessing ----------------
__global__ void k_tw1x(const float* __restrict__ w1) {
    int i = blockIdx.x * 256 + threadIdx.x;
    if (i < O1 * CC * T1) {
        int o = i / (CC * T1);
        int r = i % (CC * T1);
        int c = r / T1, t = r % T1;
        if (c >= DD) g_w1t[((c - DD) * T1 + t) * O1 + o] = w1[i];
    }
    if (i < DD * O1) {
        int c = i & 63, o = i >> 6;
        float s = 0.f;
#pragma unroll
        for (int t = 0; t < T1; t++) s += w1[(o * CC + c) * T1 + t];
        g_w1a[c * O1 + o] = s;
    }
}
__global__ void k_tw2x(const float* __restrict__ w2) {
    int i = blockIdx.x * 256 + threadIdx.x;
    if (i < O2C * CC * SS) {
        int o = i / (CC * SS);
        int r = i % (CC * SS);
        int c = r / SS, s = r % SS;
        if (s >= KK)      g_w2c[(c * KK + (s - KK)) * O2C + o] = w2[i];
        else if (c >= DD) g_w2t[((c - DD) * KK + s) * O2C + o] = w2[i];
    }
    if (i < DD * O2C) {
        int c = i & 63, o = i >> 6;
        float s = 0.f;
#pragma unroll
        for (int t = 0; t < KK; t++) s += w2[(o * CC + c) * SS + t];
        g_w2a[c * O2C + o] = s;
    }
}

// ---------------- squared norms (mul-then-add, matches ref) ----------
__global__ void k_sq(const float* __restrict__ x) {
    int i = blockIdx.x * 256 + threadIdx.x;
    if (i >= BB * NN) return;
    int b = i / NN, n = i % NN;
    const float* xb = x + (size_t)b * DD * NN + n;
    float s = 0.f;
#pragma unroll
    for (int d = 0; d < DD; d++) {
        float v = xb[(size_t)d * NN];
        s = __fadd_rn(s, __fmul_rn(v, v));
    }
    g_sq[i] = s;
}

// ---------------- kNN — packed-fma2 distances + group-parallel top-20 --------
__global__ void __launch_bounds__(256) k_knn(const float* __restrict__ x) {
    int b  = blockIdx.x / (NN / GN);
    int n0 = (blockIdx.x % (NN / GN)) * GN;
    __shared__ float xn[GN][DD];
    __shared__ float dist[GN][NN];
    __shared__ float gwv[GN][2][2];
    __shared__ int   gwi[GN][2][2];
    int tid = threadIdx.x;

    const float* xb = x + (size_t)b * DD * NN;
    for (int i = tid; i < GN * DD; i += 256) {
        int g = i / DD, d = i % DD;
        xn[g][d] = xb[(size_t)d * NN + n0 + g];
    }
    __syncthreads();

    float sqn[GN];
#pragma unroll
    for (int g = 0; g < GN; g++) sqn[g] = g_sq[b * NN + n0 + g];

    ull ddot[GN][4];
#pragma unroll
    for (int g = 0; g < GN; g++)
#pragma unroll
        for (int q = 0; q < 4; q++) ddot[g][q] = 0ull;

    for (int d = 0; d < DD; d++) {
        const ulonglong2* row2 = (const ulonglong2*)(xb + (size_t)d * NN);
        ulonglong2 A0 = row2[tid];
        ulonglong2 A1 = row2[tid + 256];
#pragma unroll
        for (int g = 0; g < GN; g++) {
            ull xn2 = dup2(xn[g][d]);
            ddot[g][0] = fma2(A0.x, xn2, ddot[g][0]);
            ddot[g][1] = fma2(A0.y, xn2, ddot[g][1]);
            ddot[g][2] = fma2(A1.x, xn2, ddot[g][2]);
            ddot[g][3] = fma2(A1.y, xn2, ddot[g][3]);
        }
    }
#pragma unroll
    for (int q = 0; q < 4; q++) {
        int mbase = 4 * tid + (q & 1) * 2 + (q >> 1) * 1024;
        float sm0 = g_sq[b * NN + mbase];
        float sm1 = g_sq[b * NN + mbase + 1];
#pragma unroll
        for (int g = 0; g < GN; g++) {
            float2 dg = unpk(ddot[g][q]);
            float t0 = __fadd_rn(sqn[g], sm0);
            float d0 = __fsub_rn(t0, __fmul_rn(2.f, dg.x));
            dist[g][mbase] = (mbase == n0 + g) ? 1e30f : d0;
            float t1 = __fadd_rn(sqn[g], sm1);
            float d1 = __fsub_rn(t1, __fmul_rn(2.f, dg.y));
            dist[g][mbase + 1] = (mbase + 1 == n0 + g) ? 1e30f : d1;
        }
    }
    __syncthreads();

    int grp = tid >> 6;
    int lg  = tid & 63;
    int gwarp = (tid >> 5) & 1;

    float bv = 1e30f; int bi = 1 << 29;
#pragma unroll 8
    for (int r = 0; r < 32; r++) {
        int m = lg + 64 * r;
        float v = dist[grp][m];
        if (v < bv || (v == bv && m < bi)) { bv = v; bi = m; }
    }
    for (int kk = 0; kk < KK; kk++) {
        float v = bv; int idx = bi;
#pragma unroll
        for (int s = 16; s; s >>= 1) {
            float vo = __shfl_xor_sync(0xffffffffu, v, s);
            int   io = __shfl_xor_sync(0xffffffffu, idx, s);
            if (vo < v || (vo == v && io < idx)) { v = vo; idx = io; }
        }
        if ((tid & 31) == 0) { gwv[grp][kk & 1][gwarp] = v; gwi[grp][kk & 1][gwarp] = idx; }
        asm volatile("bar.sync %0, 64;" :: "r"(grp + 1) : "memory");
        float v0 = gwv[grp][kk & 1][0], v1 = gwv[grp][kk & 1][1];
        int   i0 = gwi[grp][kk & 1][0], i1 = gwi[grp][kk & 1][1];
        int w = (v1 < v0 || (v1 == v0 && i1 < i0)) ? i1 : i0;
        if (lg == 0) g_idx[(b * NN + n0 + grp) * KK + kk] = w;
        if ((w & 63) == lg) {
            dist[grp][w] = 1e30f;
            bv = 1e30f; bi = 1 << 29;
#pragma unroll 8
            for (int r = 0; r < 32; r++) {
                int m = lg + 64 * r;
                float vv = dist[grp][m];
                if (vv < bv || (vv == bv && m < bi)) { bv = vv; bi = m; }
            }
        }
    }
}

// ---------------- conv1: LDG-coalesced weights, NO mainloop barriers ---------
// dyn smem: xn_s[256] + ed_s[5120] = 21.5KB
__global__ void __launch_bounds__(256, 2) k_conv1(const float* __restrict__ x,
                                                  const float* __restrict__ b1) {
    extern __shared__ float smem[];
    float* xn_s = smem;
    float* ed_s = smem + DD * G1;
    int b  = blockIdx.x / (NN / G1);
    int n0 = (blockIdx.x % (NN / G1)) * G1;
    int tid = threadIdx.x;
    const float* xb = x + (size_t)b * DD * NN;

    for (int i = tid; i < DD * G1; i += 256) {
        int c = i >> 2, g = i & 3;
        xn_s[i] = xb[(size_t)c * NN + n0 + g];
    }
    for (int i = tid; i < DD * KK * G1; i += 256) {
        int g = i & 3, m = i >> 2;
        int d = m / KK, k = m % KK;
        int n = n0 + g;
        int mm = g_idx[(b * NN + n) * KK + k];
        float v = xb[(size_t)d * NN + mm] - xb[(size_t)d * NN + n];
        ed_s[i] = v;
        g_ed[(size_t)(b * NN + n) * (DD * KK) + m] = v;
    }
    __syncthreads();

    int o = tid;
    // Part A: constant-channel GEMV
    ull accA[2] = {0ull, 0ull};
    for (int c = 0; c < DD; c += 4) {
        float w4[4];
#pragma unroll
        for (int q = 0; q < 4; q++) w4[q] = g_w1a[(c + q) * O1 + o];
#pragma unroll
        for (int q = 0; q < 4; q++) {
            ull wv = dup2(w4[q]);
            accA[0] = fma2(*(const ull*)&xn_s[(c + q) * G1 + 0], wv, accA[0]);
            accA[1] = fma2(*(const ull*)&xn_s[(c + q) * G1 + 2], wv, accA[1]);
        }
    }

    // Part B: diff-channel conv, software-pipelined coalesced weight LDGs
    ull acc[2][J1];
#pragma unroll
    for (int p = 0; p < 2; p++)
#pragma unroll
        for (int j = 0; j < J1; j++) acc[p][j] = 0ull;

    const float* wbase = g_w1t + o;          // [(c*11+t)*256 + o]
    float wf[T1];
#pragma unroll
    for (int t = 0; t < T1; t++) wf[t] = wbase[t * O1];     // prefetch c=0

    for (int c = 0; c < DD; c++) {
        ull wd[T1];
#pragma unroll
        for (int t = 0; t < T1; t++) wd[t] = dup2(wf[t]);
        if (c + 1 < DD) {
            const float* nb = wbase + (size_t)(c + 1) * T1 * O1;
#pragma unroll
            for (int t = 0; t < T1; t++) wf[t] = nb[t * O1]; // prefetch next channel
        }
        const float* ers = &ed_s[c * KK * G1];
#pragma unroll
        for (int p = 0; p < 2; p++) {
            ull wnd[T1];                     // ring: e[k] at slot k%11
#pragma unroll
            for (int t = 0; t < T1; t++)
                wnd[t] = *(const ull*)&ers[t * G1 + 2 * p];
#pragma unroll
            for (int j = 0; j < J1; j++) {
#pragma unroll
                for (int t = 0; t < T1; t++)
                    acc[p][j] = fma2(wnd[(j + t) % T1], wd[t], acc[p][j]);
                if (j < J1 - 1)
                    wnd[j % T1] = *(const ull*)&ers[(j + T1) * G1 + 2 * p];
            }
        }
    }
    float bias = b1[o];
    float2 aA0 = unpk(accA[0]), aA1 = unpk(accA[1]);
    float ax[4] = {aA0.x, aA0.y, aA1.x, aA1.y};
    float s1 = 0.f, s2 = 0.f;
#pragma unroll
    for (int p = 0; p < 2; p++)
#pragma unroll
        for (int j = 0; j < J1; j++) {
            float2 v = unpk(acc[p][j]);
            float vx = v.x + ax[2 * p]     + bias;
            float vy = v.y + ax[2 * p + 1] + bias;
            g_h[((size_t)(b * NN + n0 + 2 * p)     * J1 + j) * O1 + o] = vx;
            g_h[((size_t)(b * NN + n0 + 2 * p + 1) * J1 + j) * O1 + o] = vy;
            s1 += vx + vy; s2 += vx * vx + vy * vy;
        }
    g_p1[blockIdx.x * O1 + o] = s1;
    g_p2[blockIdx.x * O1 + o] = s2;
}

// ---------------- BN1 finalize ----------------
__global__ void k_bn1fin(const float* __restrict__ gamma, const float* __restrict__ beta) {
    int o = blockIdx.x;
    int tid = threadIdx.x;
    float s = 0.f, s2 = 0.f;
    for (int blk = tid; blk < NB1; blk += 256) {
        s  += g_p1[blk * O1 + o];
        s2 += g_p2[blk * O1 + o];
    }
    __shared__ float rs[256], rs2[256];
    rs[tid] = s; rs2[tid] = s2;
    __syncthreads();
    for (int t = 128; t > 0; t >>= 1) {
        if (tid < t) { rs[tid] += rs[tid + t]; rs2[tid] += rs2[tid + t]; }
        __syncthreads();
    }
    if (tid == 0) {
        float cnt  = (float)(BB * NN * J1);
        float mean = rs[0] / cnt;
        float var  = rs2[0] / cnt - mean * mean;
        float a    = gamma[o] * rsqrtf(var + 1e-5f);
        g_bn1a[o] = a;
        g_bn1b[o] = beta[o] - mean * a;
    }
}

// ---------------- conv2 fused, 3 blocks/SM ----------------
__global__ void __launch_bounds__(256, 3) k_conv2(const float* __restrict__ x,
                                                  const float* __restrict__ b2) {
    extern __shared__ float smem[];
    float* xs  = smem;
    float* ed2 = smem + DD * G2P;
    float* hp2 = smem + DD * G2P + C2ED * RPAD;
    int b  = blockIdx.x / (NN / G2P);
    int n0 = (blockIdx.x % (NN / G2P)) * G2P;
    int tid = threadIdx.x;
    int o2 = tid;

    {
        const float* xb = x + (size_t)b * DD * NN;
        for (int i = tid; i < DD * G2P; i += 256) {
            int c = i >> 4, g = i & 15;
            xs[i] = xb[(size_t)c * NN + n0 + g];
        }
    }

    ull acc[G2P / 2];
#pragma unroll
    for (int p = 0; p < G2P / 2; p++) acc[p] = 0ull;

    for (int pass = 0; pass < NCH; pass++) {
        if (pass > 0) __syncthreads();
        for (int i = tid; i < G2P * C2ED; i += 256) {
            int g = i / C2ED, m = i % C2ED;
            ed2[m * RPAD + g] = g_ed[(size_t)(b * NN + n0 + g) * (DD * KK) + pass * C2ED + m];
        }
        for (int i = tid; i < G2P * C2HP; i += 256) {
            int g = i / C2HP, r = i % C2HP;
            int j = r >> 6, oo = r & 63;
            int o = pass * 64 + oo;
            float raw = g_h[((size_t)(b * NN + n0 + g) * J1 + j) * O1 + o];
            float v = g_bn1a[o] * raw + g_bn1b[o];
            v = v > 0.f ? v : 0.01f * v;
            int cl = oo >> 1;
            int k  = (oo & 1) * J1 + j;
            hp2[(cl * KK + k) * RPAD + g] = v;
        }
        __syncthreads();

        if (pass == 0) {
            for (int c = 0; c < DD; c += 8) {
                float w8[8];
#pragma unroll
                for (int q = 0; q < 8; q++) w8[q] = g_w2a[(c + q) * O2C + o2];
#pragma unroll
                for (int q = 0; q < 8; q++) {
                    ull wv = dup2(w8[q]);
                    const float* xr = &xs[(c + q) * G2P];
#pragma unroll
                    for (int p = 0; p < G2P / 2; p++)
                        acc[p] = fma2(*(const ull*)&xr[2 * p], wv, acc[p]);
                }
            }
        }
        for (int dcl = 0; dcl < 16; dcl++) {
            const float* wrow = &g_w2t[((pass * 16 + dcl) * KK) * O2C + o2];
            const float* er = &ed2[dcl * KK * RPAD];
#pragma unroll
            for (int sb = 0; sb < KK; sb += 10) {
                ull wd10[10];
#pragma unroll
                for (int q = 0; q < 10; q++) wd10[q] = dup2(wrow[(sb + q) * O2C]);
#pragma unroll
                for (int q = 0; q < 10; q++) {
                    const float* row = &er[(sb + q) * RPAD];
#pragma unroll
                    for (int p = 0; p < G2P / 2; p++)
                        acc[p] = fma2(*(const ull*)&row[2 * p], wd10[q], acc[p]);
                }
            }
        }
        for (int cl = 0; cl < 32; cl++) {
            const float* wrow = &g_w2c[((pass * 32 + cl) * KK) * O2C + o2];
            const float* hr = &hp2[cl * KK * RPAD];
#pragma unroll
            for (int sb = 0; sb < KK; sb += 10) {
                ull wd10[10];
#pragma unroll
                for (int q = 0; q < 10; q++) wd10[q] = dup2(wrow[(sb + q) * O2C]);
#pragma unroll
                for (int q = 0; q < 10; q++) {
                    const float* row = &hr[(sb + q) * RPAD];
#pragma unroll
                    for (int p = 0; p < G2P / 2; p++)
                        acc[p] = fma2(*(const ull*)&row[2 * p], wd10[q], acc[p]);
                }
            }
        }
    }

    float bias = b2[o2];
    float s1 = 0.f, s2 = 0.f;
#pragma unroll
    for (int p = 0; p < G2P / 2; p++) {
        float2 v = unpk(acc[p]);
        float yx = v.x + bias, yy = v.y + bias;
        g_y[(b * NN + n0 + 2 * p)     * O2C + o2] = yx;
        g_y[(b * NN + n0 + 2 * p + 1) * O2C + o2] = yy;
        s1 += yx + yy; s2 += yx * yx + yy * yy;
    }
    g_q1[blockIdx.x * O2C + o2] = s1;
    g_q2[blockIdx.x * O2C + o2] = s2;
}

// ---------------- BN2 finalize ----------------
__global__ void k_bn2fin(const float* __restrict__ gamma, const float* __restrict__ beta) {
    int o = blockIdx.x;
    int tid = threadIdx.x;
    float s = 0.f, s2 = 0.f;
    for (int blk = tid; blk < NB2; blk += 256) {
        s  += g_q1[blk * O2C + o];
        s2 += g_q2[blk * O2C + o];
    }
    __shared__ float rs[256], rs2[256];
    rs[tid] = s; rs2[tid] = s2;
    __syncthreads();
    for (int t = 128; t > 0; t >>= 1) {
        if (tid < t) { rs[tid] += rs[tid + t]; rs2[tid] += rs2[tid + t]; }
        __syncthreads();
    }
    if (tid == 0) {
        float cnt  = (float)(BB * NN);
        float mean = rs[0] / cnt;
        float var  = rs2[0] / cnt - mean * mean;
        float a    = gamma[o] * rsqrtf(var + 1e-5f);
        g_bn2a[o] = a;
        g_bn2b[o] = beta[o] - mean * a;
    }
}

// ---------------- output: tiled transpose ----------------
__global__ void __launch_bounds__(256) k_out(float* __restrict__ out) {
    __shared__ float sy[32 * 257];
    int b  = blockIdx.x >> 6;
    int n0 = (blockIdx.x & 63) * 32;
    int tid = threadIdx.x;

    for (int it = 0; it < 32; it++) {
        int g = it, o2 = tid;
        float v = g_y[(b * NN + n0 + g) * O2C + o2];
        v = g_bn2a[o2] * v + g_bn2b[o2];
        sy[g * 257 + o2] = v > 0.f ? v : 0.f;
    }
    __syncthreads();
    float* ob = out + (size_t)b * 524288;
    for (int it = 0; it < 32; it++) {
        int row = (tid >> 5) + it * 8;
        int g   = tid & 31;
        ob[(row >> 1) * 4096 + (row & 1) * 2048 + n0 + g] = sy[g * 257 + row];
    }
}

// ---------------- launch ----------------
extern "C" void kernel_launch(void* const* d_in, const int* in_sizes, int n_in,
                              void* d_out, int out_size) {
    const float* x   = (const float*)d_in[0];
    const float* w1  = (const float*)d_in[1];
    const float* b1  = (const float*)d_in[2];
    const float* g1  = (const float*)d_in[3];
    const float* be1 = (const float*)d_in[4];
    const float* w2  = (const float*)d_in[5];
    const float* b2  = (const float*)d_in[6];
    const float* g2  = (const float*)d_in[7];
    const float* be2 = (const float*)d_in[8];
    float* out = (float*)d_out;

    static int attr_done = 0;
    int smem1 = (DD * G1 + DD * KK * G1) * (int)sizeof(float);            // 21.5KB
    int smem2 = (DD * G2P + (C2ED + C2HP) * RPAD) * (int)sizeof(float);   // 73.2KB
    if (!attr_done) {
        cudaFuncSetAttribute(k_conv1, cudaFuncAttributeMaxDynamicSharedMemorySize, smem1);
        cudaFuncSetAttribute(k_conv2, cudaFuncAttributeMaxDynamicSharedMemorySize, smem2);
        attr_done = 1;
    }

    // conv1 stays the 4th launch for ncu visibility
    k_tw1x<<<(O1 * CC * T1 + 255) / 256, 256>>>(w1);
    k_sq  <<<(BB * NN + 255) / 256, 256>>>(x);
    k_knn <<<BB * NN / GN, 256>>>(x);
    k_conv1<<<NB1, 256, smem1>>>(x, b1);
    k_tw2x<<<(O2C * CC * SS + 255) / 256, 256>>>(w2);
    k_bn1fin<<<O1, 256>>>(g1, be1);
    k_conv2<<<NB2, 256, smem2>>>(x, b2);
    k_bn2fin<<<O2C, 256>>>(g2, be2);
    k_out <<<BB * 64, 256>>>(out);
}

// round 14
// speedup vs baseline: 1.0520x; 1.0520x over previous
#include <cuda_runtime.h>
#include <math.h>
#include <stdint.h>

// Problem constants
#define BB   8
#define DD   64
#define NN   2048
#define KK   20
#define CC   128
#define O1   256
#define J1   10
#define T1   11
#define O2C  256
#define SS   40
#define GN   4
#define G1   4
#define G2P  16
#define NCH  4
#define RPAD 18
#define NB1  (BB * NN / G1)
#define NB2  (BB * NN / G2P)
#define C2HP (32 * KK)
#define C2ED (16 * KK)

typedef unsigned long long ull;

__device__ __forceinline__ ull fma2(ull a, ull b, ull c) {
    ull d;
    asm("fma.rn.f32x2 %0, %1, %2, %3;" : "=l"(d) : "l"(a), "l"(b), "l"(c));
    return d;
}
__device__ __forceinline__ ull dup2(float v) {
    ull d; unsigned int u = __float_as_uint(v);
    asm("mov.b64 %0, {%1, %1};" : "=l"(d) : "r"(u));
    return d;
}
__device__ __forceinline__ float2 unpk(ull v) {
    float2 r;
    asm("mov.b64 {%0, %1}, %2;" : "=f"(r.x), "=f"(r.y) : "l"(v));
    return r;
}

// ---------------- scratch ----------------
__device__ float g_sq[BB * NN];
__device__ int   g_idx[BB * NN * KK];
__device__ float g_ed[(size_t)BB * NN * 64 * KK];
__device__ float g_h [(size_t)BB * NN * J1 * O1];   // [b][n][j][o]
__device__ float g_bn1a[O1];
__device__ float g_bn1b[O1];
__device__ float g_y [BB * NN * O2C];
__device__ float g_bn2a[O2C];
__device__ float g_bn2b[O2C];
__device__ float g_w1t[64 * T1 * O1];               // [c][t][o]  (o-coalesced)
__device__ float g_w1a[64 * O1];
__device__ float g_w2t[64 * KK * O2C];
__device__ float g_w2c[CC * KK * O2C];
__device__ float g_w2a[64 * O2C];
__device__ float g_p1[NB1 * O1];
__device__ float g_p2[NB1 * O1];
__device__ float g_q1[NB2 * O2C];
__device__ float g_q2[NB2 * O2C];

// ---------------- weight preprocessing ----------------
__global__ void k_tw1x(const float* __restrict__ w1) {
    int i = blockIdx.x * 256 + threadIdx.x;
    if (i < O1 * CC * T1) {
        int o = i / (CC * T1);
        int r = i % (CC * T1);
        int c = r / T1, t = r % T1;
        if (c >= DD) g_w1t[((c - DD) * T1 + t) * O1 + o] = w1[i];
    }
    if (i < DD * O1) {
        int c = i & 63, o = i >> 6;
        float s = 0.f;
#pragma unroll
        for (int t = 0; t < T1; t++) s += w1[(o * CC + c) * T1 + t];
        g_w1a[c * O1 + o] = s;
    }
}
__global__ void k_tw2x(const float* __restrict__ w2) {
    int i = blockIdx.x * 256 + threadIdx.x;
    if (i < O2C * CC * SS) {
        int o = i / (CC * SS);
        int r = i % (CC * SS);
        int c = r / SS, s = r % SS;
        if (s >= KK)      g_w2c[(c * KK + (s - KK)) * O2C + o] = w2[i];
        else if (c >= DD) g_w2t[((c - DD) * KK + s) * O2C + o] = w2[i];
    }
    if (i < DD * O2C) {
        int c = i & 63, o = i >> 6;
        float s = 0.f;
#pragma unroll
        for (int t = 0; t < KK; t++) s += w2[(o * CC + c) * SS + t];
        g_w2a[c * O2C + o] = s;
    }
}

// ---------------- squared norms (mul-then-add, matches ref) ----------
__global__ void k_sq(const float* __restrict__ x) {
    int i = blockIdx.x * 256 + threadIdx.x;
    if (i >= BB * NN) return;
    int b = i / NN, n = i % NN;
    const float* xb = x + (size_t)b * DD * NN + n;
    float s = 0.f;
#pragma unroll
    for (int d = 0; d < DD; d++) {
        float v = xb[(size_t)d * NN];
        s = __fadd_rn(s, __fmul_rn(v, v));
    }
    g_sq[i] = s;
}

// ---------------- kNN — packed-fma2 distances + group-parallel top-20 --------
__global__ void __launch_bounds__(256) k_knn(const float* __restrict__ x) {
    int b  = blockIdx.x / (NN / GN);
    int n0 = (blockIdx.x % (NN / GN)) * GN;
    __shared__ float xn[GN][DD];
    __shared__ float dist[GN][NN];
    __shared__ float gwv[GN][2][2];
    __shared__ int   gwi[GN][2][2];
    int tid = threadIdx.x;

    const float* xb = x + (size_t)b * DD * NN;
    for (int i = tid; i < GN * DD; i += 256) {
        int g = i / DD, d = i % DD;
        xn[g][d] = xb[(size_t)d * NN + n0 + g];
    }
    __syncthreads();

    float sqn[GN];
#pragma unroll
    for (int g = 0; g < GN; g++) sqn[g] = g_sq[b * NN + n0 + g];

    ull ddot[GN][4];
#pragma unroll
    for (int g = 0; g < GN; g++)
#pragma unroll
        for (int q = 0; q < 4; q++) ddot[g][q] = 0ull;

    for (int d = 0; d < DD; d++) {
        const ulonglong2* row2 = (const ulonglong2*)(xb + (size_t)d * NN);
        ulonglong2 A0 = row2[tid];
        ulonglong2 A1 = row2[tid + 256];
#pragma unroll
        for (int g = 0; g < GN; g++) {
            ull xn2 = dup2(xn[g][d]);
            ddot[g][0] = fma2(A0.x, xn2, ddot[g][0]);
            ddot[g][1] = fma2(A0.y, xn2, ddot[g][1]);
            ddot[g][2] = fma2(A1.x, xn2, ddot[g][2]);
            ddot[g][3] = fma2(A1.y, xn2, ddot[g][3]);
        }
    }
#pragma unroll
    for (int q = 0; q < 4; q++) {
        int mbase = 4 * tid + (q & 1) * 2 + (q >> 1) * 1024;
        float sm0 = g_sq[b * NN + mbase];
        float sm1 = g_sq[b * NN + mbase + 1];
#pragma unroll
        for (int g = 0; g < GN; g++) {
            float2 dg = unpk(ddot[g][q]);
            float t0 = __fadd_rn(sqn[g], sm0);
            float d0 = __fsub_rn(t0, __fmul_rn(2.f, dg.x));
            dist[g][mbase] = (mbase == n0 + g) ? 1e30f : d0;
            float t1 = __fadd_rn(sqn[g], sm1);
            float d1 = __fsub_rn(t1, __fmul_rn(2.f, dg.y));
            dist[g][mbase + 1] = (mbase + 1 == n0 + g) ? 1e30f : d1;
        }
    }
    __syncthreads();

    int grp = tid >> 6;
    int lg  = tid & 63;
    int gwarp = (tid >> 5) & 1;

    float bv = 1e30f; int bi = 1 << 29;
#pragma unroll 8
    for (int r = 0; r < 32; r++) {
        int m = lg + 64 * r;
        float v = dist[grp][m];
        if (v < bv || (v == bv && m < bi)) { bv = v; bi = m; }
    }
    for (int kk = 0; kk < KK; kk++) {
        float v = bv; int idx = bi;
#pragma unroll
        for (int s = 16; s; s >>= 1) {
            float vo = __shfl_xor_sync(0xffffffffu, v, s);
            int   io = __shfl_xor_sync(0xffffffffu, idx, s);
            if (vo < v || (vo == v && io < idx)) { v = vo; idx = io; }
        }
        if ((tid & 31) == 0) { gwv[grp][kk & 1][gwarp] = v; gwi[grp][kk & 1][gwarp] = idx; }
        asm volatile("bar.sync %0, 64;" :: "r"(grp + 1) : "memory");
        float v0 = gwv[grp][kk & 1][0], v1 = gwv[grp][kk & 1][1];
        int   i0 = gwi[grp][kk & 1][0], i1 = gwi[grp][kk & 1][1];
        int w = (v1 < v0 || (v1 == v0 && i1 < i0)) ? i1 : i0;
        if (lg == 0) g_idx[(b * NN + n0 + grp) * KK + kk] = w;
        if ((w & 63) == lg) {
            dist[grp][w] = 1e30f;
            bv = 1e30f; bi = 1 << 29;
#pragma unroll 8
            for (int r = 0; r < 32; r++) {
                int m = lg + 64 * r;
                float vv = dist[grp][m];
                if (vv < bv || (vv == bv && m < bi)) { bv = vv; bi = m; }
            }
        }
    }
}

// ---------------- conv1: barrier-free + p-outer split -> 3 blocks/SM --------
// dyn smem: xn_s[256] + ed_s[5120] = 21.5KB
__global__ void __launch_bounds__(256, 3) k_conv1(const float* __restrict__ x,
                                                  const float* __restrict__ b1) {
    extern __shared__ float smem[];
    float* xn_s = smem;
    float* ed_s = smem + DD * G1;
    int b  = blockIdx.x / (NN / G1);
    int n0 = (blockIdx.x % (NN / G1)) * G1;
    int tid = threadIdx.x;
    const float* xb = x + (size_t)b * DD * NN;

    for (int i = tid; i < DD * G1; i += 256) {
        int c = i >> 2, g = i & 3;
        xn_s[i] = xb[(size_t)c * NN + n0 + g];
    }
    for (int i = tid; i < DD * KK * G1; i += 256) {
        int g = i & 3, m = i >> 2;
        int d = m / KK, k = m % KK;
        int n = n0 + g;
        int mm = g_idx[(b * NN + n) * KK + k];
        float v = xb[(size_t)d * NN + mm] - xb[(size_t)d * NN + n];
        ed_s[i] = v;
        g_ed[(size_t)(b * NN + n) * (DD * KK) + m] = v;
    }
    __syncthreads();

    int o = tid;
    // Part A: constant-channel GEMV (both pairs; tiny)
    ull accA[2] = {0ull, 0ull};
    for (int c = 0; c < DD; c += 4) {
        float w4[4];
#pragma unroll
        for (int q = 0; q < 4; q++) w4[q] = g_w1a[(c + q) * O1 + o];
#pragma unroll
        for (int q = 0; q < 4; q++) {
            ull wv = dup2(w4[q]);
            accA[0] = fma2(*(const ull*)&xn_s[(c + q) * G1 + 0], wv, accA[0]);
            accA[1] = fma2(*(const ull*)&xn_s[(c + q) * G1 + 2], wv, accA[1]);
        }
    }
    float2 aA0 = unpk(accA[0]), aA1 = unpk(accA[1]);
    float ax[4] = {aA0.x, aA0.y, aA1.x, aA1.y};
    float bias = b1[o];
    float s1 = 0.f, s2 = 0.f;
    const float* wbase = g_w1t + o;          // [(c*11+t)*256 + o]

    // Part B: one point-pair at a time (low regs -> 3 blocks/SM)
    for (int p = 0; p < 2; p++) {
        ull acc[J1];
#pragma unroll
        for (int j = 0; j < J1; j++) acc[j] = 0ull;

        for (int c = 0; c < DD; c++) {
            const float* wc = wbase + (size_t)c * T1 * O1;
            ull wd[T1];
#pragma unroll
            for (int t = 0; t < T1; t++) wd[t] = dup2(wc[t * O1]);  // coalesced LDG
            const float* ers = &ed_s[c * KK * G1];
            ull wnd[T1];                     // ring: e[k] at slot k%11
#pragma unroll
            for (int t = 0; t < T1; t++)
                wnd[t] = *(const ull*)&ers[t * G1 + 2 * p];
#pragma unroll
            for (int j = 0; j < J1; j++) {
#pragma unroll
                for (int t = 0; t < T1; t++)
                    acc[j] = fma2(wnd[(j + t) % T1], wd[t], acc[j]);
                if (j < J1 - 1)
                    wnd[j % T1] = *(const ull*)&ers[(j + T1) * G1 + 2 * p];
            }
        }
#pragma unroll
        for (int j = 0; j < J1; j++) {
            float2 v = unpk(acc[j]);
            float vx = v.x + ax[2 * p]     + bias;
            float vy = v.y + ax[2 * p + 1] + bias;
            g_h[((size_t)(b * NN + n0 + 2 * p)     * J1 + j) * O1 + o] = vx;
            g_h[((size_t)(b * NN + n0 + 2 * p + 1) * J1 + j) * O1 + o] = vy;
            s1 += vx + vy; s2 += vx * vx + vy * vy;
        }
    }
    g_p1[blockIdx.x * O1 + o] = s1;
    g_p2[blockIdx.x * O1 + o] = s2;
}

// ---------------- BN1 finalize ----------------
__global__ void k_bn1fin(const float* __restrict__ gamma, const float* __restrict__ beta) {
    int o = blockIdx.x;
    int tid = threadIdx.x;
    float s = 0.f, s2 = 0.f;
    for (int blk = tid; blk < NB1; blk += 256) {
        s  += g_p1[blk * O1 + o];
        s2 += g_p2[blk * O1 + o];
    }
    __shared__ float rs[256], rs2[256];
    rs[tid] = s; rs2[tid] = s2;
    __syncthreads();
    for (int t = 128; t > 0; t >>= 1) {
        if (tid < t) { rs[tid] += rs[tid + t]; rs2[tid] += rs2[tid + t]; }
        __syncthreads();
    }
    if (tid == 0) {
        float cnt  = (float)(BB * NN * J1);
        float mean = rs[0] / cnt;
        float var  = rs2[0] / cnt - mean * mean;
        float a    = gamma[o] * rsqrtf(var + 1e-5f);
        g_bn1a[o] = a;
        g_bn1b[o] = beta[o] - mean * a;
    }
}

// ---------------- conv2 fused, 3 blocks/SM ----------------
__global__ void __launch_bounds__(256, 3) k_conv2(const float* __restrict__ x,
                                                  const float* __restrict__ b2) {
    extern __shared__ float smem[];
    float* xs  = smem;
    float* ed2 = smem + DD * G2P;
    float* hp2 = smem + DD * G2P + C2ED * RPAD;
    int b  = blockIdx.x / (NN / G2P);
    int n0 = (blockIdx.x % (NN / G2P)) * G2P;
    int tid = threadIdx.x;
    int o2 = tid;

    {
        const float* xb = x + (size_t)b * DD * NN;
        for (int i = tid; i < DD * G2P; i += 256) {
            int c = i >> 4, g = i & 15;
            xs[i] = xb[(size_t)c * NN + n0 + g];
        }
    }

    ull acc[G2P / 2];
#pragma unroll
    for (int p = 0; p < G2P / 2; p++) acc[p] = 0ull;

    for (int pass = 0; pass < NCH; pass++) {
        if (pass > 0) __syncthreads();
        for (int i = tid; i < G2P * C2ED; i += 256) {
            int g = i / C2ED, m = i % C2ED;
            ed2[m * RPAD + g] = g_ed[(size_t)(b * NN + n0 + g) * (DD * KK) + pass * C2ED + m];
        }
        for (int i = tid; i < G2P * C2HP; i += 256) {
            int g = i / C2HP, r = i % C2HP;
            int j = r >> 6, oo = r & 63;
            int o = pass * 64 + oo;
            float raw = g_h[((size_t)(b * NN + n0 + g) * J1 + j) * O1 + o];
            float v = g_bn1a[o] * raw + g_bn1b[o];
            v = v > 0.f ? v : 0.01f * v;
            int cl = oo >> 1;
            int k  = (oo & 1) * J1 + j;
            hp2[(cl * KK + k) * RPAD + g] = v;
        }
        __syncthreads();

        if (pass == 0) {
            for (int c = 0; c < DD; c += 8) {
                float w8[8];
#pragma unroll
                for (int q = 0; q < 8; q++) w8[q] = g_w2a[(c + q) * O2C + o2];
#pragma unroll
                for (int q = 0; q < 8; q++) {
                    ull wv = dup2(w8[q]);
                    const float* xr = &xs[(c + q) * G2P];
#pragma unroll
                    for (int p = 0; p < G2P / 2; p++)
                        acc[p] = fma2(*(const ull*)&xr[2 * p], wv, acc[p]);
                }
            }
        }
        for (int dcl = 0; dcl < 16; dcl++) {
            const float* wrow = &g_w2t[((pass * 16 + dcl) * KK) * O2C + o2];
            const float* er = &ed2[dcl * KK * RPAD];
#pragma unroll
            for (int sb = 0; sb < KK; sb += 10) {
                ull wd10[10];
#pragma unroll
                for (int q = 0; q < 10; q++) wd10[q] = dup2(wrow[(sb + q) * O2C]);
#pragma unroll
                for (int q = 0; q < 10; q++) {
                    const float* row = &er[(sb + q) * RPAD];
#pragma unroll
                    for (int p = 0; p < G2P / 2; p++)
                        acc[p] = fma2(*(const ull*)&row[2 * p], wd10[q], acc[p]);
                }
            }
        }
        for (int cl = 0; cl < 32; cl++) {
            const float* wrow = &g_w2c[((pass * 32 + cl) * KK) * O2C + o2];
            const float* hr = &hp2[cl * KK * RPAD];
#pragma unroll
            for (int sb = 0; sb < KK; sb += 10) {
                ull wd10[10];
#pragma unroll
                for (int q = 0; q < 10; q++) wd10[q] = dup2(wrow[(sb + q) * O2C]);
#pragma unroll
                for (int q = 0; q < 10; q++) {
                    const float* row = &hr[(sb + q) * RPAD];
#pragma unroll
                    for (int p = 0; p < G2P / 2; p++)
                        acc[p] = fma2(*(const ull*)&row[2 * p], wd10[q], acc[p]);
                }
            }
        }
    }

    float bias = b2[o2];
    float s1 = 0.f, s2 = 0.f;
#pragma unroll
    for (int p = 0; p < G2P / 2; p++) {
        float2 v = unpk(acc[p]);
        float yx = v.x + bias, yy = v.y + bias;
        g_y[(b * NN + n0 + 2 * p)     * O2C + o2] = yx;
        g_y[(b * NN + n0 + 2 * p + 1) * O2C + o2] = yy;
        s1 += yx + yy; s2 += yx * yx + yy * yy;
    }
    g_q1[blockIdx.x * O2C + o2] = s1;
    g_q2[blockIdx.x * O2C + o2] = s2;
}

// ---------------- BN2 finalize ----------------
__global__ void k_bn2fin(const float* __restrict__ gamma, const float* __restrict__ beta) {
    int o = blockIdx.x;
    int tid = threadIdx.x;
    float s = 0.f, s2 = 0.f;
    for (int blk = tid; blk < NB2; blk += 256) {
        s  += g_q1[blk * O2C + o];
        s2 += g_q2[blk * O2C + o];
    }
    __shared__ float rs[256], rs2[256];
    rs[tid] = s; rs2[tid] = s2;
    __syncthreads();
    for (int t = 128; t > 0; t >>= 1) {
        if (tid < t) { rs[tid] += rs[tid + t]; rs2[tid] += rs2[tid + t]; }
        __syncthreads();
    }
    if (tid == 0) {
        float cnt  = (float)(BB * NN);
        float mean = rs[0] / cnt;
        float var  = rs2[0] / cnt - mean * mean;
        float a    = gamma[o] * rsqrtf(var + 1e-5f);
        g_bn2a[o] = a;
        g_bn2b[o] = beta[o] - mean * a;
    }
}

// ---------------- output: tiled transpose ----------------
__global__ void __launch_bounds__(256) k_out(float* __restrict__ out) {
    __shared__ float sy[32 * 257];
    int b  = blockIdx.x >> 6;
    int n0 = (blockIdx.x & 63) * 32;
    int tid = threadIdx.x;

    for (int it = 0; it < 32; it++) {
        int g = it, o2 = tid;
        float v = g_y[(b * NN + n0 + g) * O2C + o2];
        v = g_bn2a[o2] * v + g_bn2b[o2];
        sy[g * 257 + o2] = v > 0.f ? v : 0.f;
    }
    __syncthreads();
    float* ob = out + (size_t)b * 524288;
    for (int it = 0; it < 32; it++) {
        int row = (tid >> 5) + it * 8;
        int g   = tid & 31;
        ob[(row >> 1) * 4096 + (row & 1) * 2048 + n0 + g] = sy[g * 257 + row];
    }
}

// ---------------- launch ----------------
extern "C" void kernel_launch(void* const* d_in, const int* in_sizes, int n_in,
                              void* d_out, int out_size) {
    const float* x   = (const float*)d_in[0];
    const float* w1  = (const float*)d_in[1];
    const float* b1  = (const float*)d_in[2];
    const float* g1  = (const float*)d_in[3];
    const float* be1 = (const float*)d_in[4];
    const float* w2  = (const float*)d_in[5];
    const float* b2  = (const float*)d_in[6];
    const float* g2  = (const float*)d_in[7];
    const float* be2 = (const float*)d_in[8];
    float* out = (float*)d_out;

    static int attr_done = 0;
    int smem1 = (DD * G1 + DD * KK * G1) * (int)sizeof(float);            // 21.5KB
    int smem2 = (DD * G2P + (C2ED + C2HP) * RPAD) * (int)sizeof(float);   // 73.2KB
    if (!attr_done) {
        cudaFuncSetAttribute(k_conv1, cudaFuncAttributeMaxDynamicSharedMemorySize, smem1);
        cudaFuncSetAttribute(k_conv2, cudaFuncAttributeMaxDynamicSharedMemorySize, smem2);
        attr_done = 1;
    }

    // conv1 stays the 4th launch for ncu visibility
    k_tw1x<<<(O1 * CC * T1 + 255) / 256, 256>>>(w1);
    k_sq  <<<(BB * NN + 255) / 256, 256>>>(x);
    k_knn <<<BB * NN / GN, 256>>>(x);
    k_conv1<<<NB1, 256, smem1>>>(x, b1);
    k_tw2x<<<(O2C * CC * SS + 255) / 256, 256>>>(w2);
    k_bn1fin<<<O1, 256>>>(g1, be1);
    k_conv2<<<NB2, 256, smem2>>>(x, b2);
    k_bn2fin<<<O2C, 256>>>(g2, be2);
    k_out <<<BB * 64, 256>>>(out);
}

// round 15
// speedup vs baseline: 1.1063x; 1.0516x over previous
#include <cuda_runtime.h>
#include <math.h>
#include <stdint.h>

// Problem constants
#define BB   8
#define DD   64
#define NN   2048
#define KK   20
#define CC   128
#define O1   256
#define J1   10
#define T1   11
#define O2C  256
#define SS   40
#define GN   4
#define G1   4
#define G2P  16
#define NCH  4
#define RPAD 18
#define NB1  (BB * NN / G1)
#define NB2  (BB * NN / G2P)
#define C2HP (32 * KK)
#define C2ED (16 * KK)

typedef unsigned long long ull;

__device__ __forceinline__ ull fma2(ull a, ull b, ull c) {
    ull d;
    asm("fma.rn.f32x2 %0, %1, %2, %3;" : "=l"(d) : "l"(a), "l"(b), "l"(c));
    return d;
}
__device__ __forceinline__ ull dup2(float v) {
    ull d; unsigned int u = __float_as_uint(v);
    asm("mov.b64 %0, {%1, %1};" : "=l"(d) : "r"(u));
    return d;
}
__device__ __forceinline__ float2 unpk(ull v) {
    float2 r;
    asm("mov.b64 {%0, %1}, %2;" : "=f"(r.x), "=f"(r.y) : "l"(v));
    return r;
}

// ---------------- scratch ----------------
__device__ float g_sq[BB * NN];
__device__ int   g_idx[BB * NN * KK];
__device__ float g_ed[(size_t)BB * NN * 64 * KK];
__device__ float g_h [(size_t)BB * NN * J1 * O1];   // [b][n][j][o]
__device__ float g_bn1a[O1];
__device__ float g_bn1b[O1];
__device__ float g_y [BB * NN * O2C];
__device__ float g_bn2a[O2C];
__device__ float g_bn2b[O2C];
__device__ float g_w1t[64 * T1 * O1];               // [c][t][o]  (o-coalesced)
__device__ float g_w1a[64 * O1];
__device__ float g_w2t[64 * KK * O2C];
__device__ float g_w2c[CC * KK * O2C];
__device__ float g_w2a[64 * O2C];
__device__ float g_p1[NB1 * O1];
__device__ float g_p2[NB1 * O1];
__device__ float g_q1[NB2 * O2C];
__device__ float g_q2[NB2 * O2C];

// ---------------- weight preprocessing ----------------
__global__ void k_tw1x(const float* __restrict__ w1) {
    int i = blockIdx.x * 256 + threadIdx.x;
    if (i < O1 * CC * T1) {
        int o = i / (CC * T1);
        int r = i % (CC * T1);
        int c = r / T1, t = r % T1;
        if (c >= DD) g_w1t[((c - DD) * T1 + t) * O1 + o] = w1[i];
    }
    if (i < DD * O1) {
        int c = i & 63, o = i >> 6;
        float s = 0.f;
#pragma unroll
        for (int t = 0; t < T1; t++) s += w1[(o * CC + c) * T1 + t];
        g_w1a[c * O1 + o] = s;
    }
}
__global__ void k_tw2x(const float* __restrict__ w2) {
    int i = blockIdx.x * 256 + threadIdx.x;
    if (i < O2C * CC * SS) {
        int o = i / (CC * SS);
        int r = i % (CC * SS);
        int c = r / SS, s = r % SS;
        if (s >= KK)      g_w2c[(c * KK + (s - KK)) * O2C + o] = w2[i];
        else if (c >= DD) g_w2t[((c - DD) * KK + s) * O2C + o] = w2[i];
    }
    if (i < DD * O2C) {
        int c = i & 63, o = i >> 6;
        float s = 0.f;
#pragma unroll
        for (int t = 0; t < KK; t++) s += w2[(o * CC + c) * SS + t];
        g_w2a[c * O2C + o] = s;
    }
}

// ---------------- squared norms (mul-then-add, matches ref) ----------
__global__ void k_sq(const float* __restrict__ x) {
    int i = blockIdx.x * 256 + threadIdx.x;
    if (i >= BB * NN) return;
    int b = i / NN, n = i % NN;
    const float* xb = x + (size_t)b * DD * NN + n;
    float s = 0.f;
#pragma unroll
    for (int d = 0; d < DD; d++) {
        float v = xb[(size_t)d * NN];
        s = __fadd_rn(s, __fmul_rn(v, v));
    }
    g_sq[i] = s;
}

// ---------------- kNN — packed-fma2 distances + group-parallel top-20 --------
__global__ void __launch_bounds__(256) k_knn(const float* __restrict__ x) {
    int b  = blockIdx.x / (NN / GN);
    int n0 = (blockIdx.x % (NN / GN)) * GN;
    __shared__ float xn[GN][DD];
    __shared__ float dist[GN][NN];
    __shared__ float gwv[GN][2][2];
    __shared__ int   gwi[GN][2][2];
    int tid = threadIdx.x;

    const float* xb = x + (size_t)b * DD * NN;
    for (int i = tid; i < GN * DD; i += 256) {
        int g = i / DD, d = i % DD;
        xn[g][d] = xb[(size_t)d * NN + n0 + g];
    }
    __syncthreads();

    float sqn[GN];
#pragma unroll
    for (int g = 0; g < GN; g++) sqn[g] = g_sq[b * NN + n0 + g];

    ull ddot[GN][4];
#pragma unroll
    for (int g = 0; g < GN; g++)
#pragma unroll
        for (int q = 0; q < 4; q++) ddot[g][q] = 0ull;

    for (int d = 0; d < DD; d++) {
        const ulonglong2* row2 = (const ulonglong2*)(xb + (size_t)d * NN);
        ulonglong2 A0 = row2[tid];
        ulonglong2 A1 = row2[tid + 256];
#pragma unroll
        for (int g = 0; g < GN; g++) {
            ull xn2 = dup2(xn[g][d]);
            ddot[g][0] = fma2(A0.x, xn2, ddot[g][0]);
            ddot[g][1] = fma2(A0.y, xn2, ddot[g][1]);
            ddot[g][2] = fma2(A1.x, xn2, ddot[g][2]);
            ddot[g][3] = fma2(A1.y, xn2, ddot[g][3]);
        }
    }
#pragma unroll
    for (int q = 0; q < 4; q++) {
        int mbase = 4 * tid + (q & 1) * 2 + (q >> 1) * 1024;
        float sm0 = g_sq[b * NN + mbase];
        float sm1 = g_sq[b * NN + mbase + 1];
#pragma unroll
        for (int g = 0; g < GN; g++) {
            float2 dg = unpk(ddot[g][q]);
            float t0 = __fadd_rn(sqn[g], sm0);
            float d0 = __fsub_rn(t0, __fmul_rn(2.f, dg.x));
            dist[g][mbase] = (mbase == n0 + g) ? 1e30f : d0;
            float t1 = __fadd_rn(sqn[g], sm1);
            float d1 = __fsub_rn(t1, __fmul_rn(2.f, dg.y));
            dist[g][mbase + 1] = (mbase + 1 == n0 + g) ? 1e30f : d1;
        }
    }
    __syncthreads();

    int grp = tid >> 6;
    int lg  = tid & 63;
    int gwarp = (tid >> 5) & 1;

    float bv = 1e30f; int bi = 1 << 29;
#pragma unroll 8
    for (int r = 0; r < 32; r++) {
        int m = lg + 64 * r;
        float v = dist[grp][m];
        if (v < bv || (v == bv && m < bi)) { bv = v; bi = m; }
    }
    for (int kk = 0; kk < KK; kk++) {
        float v = bv; int idx = bi;
#pragma unroll
        for (int s = 16; s; s >>= 1) {
            float vo = __shfl_xor_sync(0xffffffffu, v, s);
            int   io = __shfl_xor_sync(0xffffffffu, idx, s);
            if (vo < v || (vo == v && io < idx)) { v = vo; idx = io; }
        }
        if ((tid & 31) == 0) { gwv[grp][kk & 1][gwarp] = v; gwi[grp][kk & 1][gwarp] = idx; }
        asm volatile("bar.sync %0, 64;" :: "r"(grp + 1) : "memory");
        float v0 = gwv[grp][kk & 1][0], v1 = gwv[grp][kk & 1][1];
        int   i0 = gwi[grp][kk & 1][0], i1 = gwi[grp][kk & 1][1];
        int w = (v1 < v0 || (v1 == v0 && i1 < i0)) ? i1 : i0;
        if (lg == 0) g_idx[(b * NN + n0 + grp) * KK + kk] = w;
        if ((w & 63) == lg) {
            dist[grp][w] = 1e30f;
            bv = 1e30f; bi = 1 << 29;
#pragma unroll 8
            for (int r = 0; r < 32; r++) {
                int m = lg + 64 * r;
                float vv = dist[grp][m];
                if (vv < bv || (vv == bv && m < bi)) { bv = vv; bi = m; }
            }
        }
    }
}

// ---------------- conv1: barrier-free, p-outer, 4 blocks/SM ----------------
// dyn smem: xn_s[256] + ed_s[5120] = 21.5KB
__global__ void __launch_bounds__(256, 4) k_conv1(const float* __restrict__ x,
                                                  const float* __restrict__ b1) {
    extern __shared__ float smem[];
    float* xn_s = smem;
    float* ed_s = smem + DD * G1;
    int b  = blockIdx.x / (NN / G1);
    int n0 = (blockIdx.x % (NN / G1)) * G1;
    int tid = threadIdx.x;
    const float* xb = x + (size_t)b * DD * NN;

    for (int i = tid; i < DD * G1; i += 256) {
        int c = i >> 2, g = i & 3;
        xn_s[i] = xb[(size_t)c * NN + n0 + g];
    }
    for (int i = tid; i < DD * KK * G1; i += 256) {
        int g = i & 3, m = i >> 2;
        int d = m / KK, k = m % KK;
        int n = n0 + g;
        int mm = g_idx[(b * NN + n) * KK + k];
        float v = xb[(size_t)d * NN + mm] - xb[(size_t)d * NN + n];
        ed_s[i] = v;
        g_ed[(size_t)(b * NN + n) * (DD * KK) + m] = v;
    }
    __syncthreads();

    int o = tid;
    ull accA[2] = {0ull, 0ull};
    for (int c = 0; c < DD; c += 4) {
        float w4[4];
#pragma unroll
        for (int q = 0; q < 4; q++) w4[q] = g_w1a[(c + q) * O1 + o];
#pragma unroll
        for (int q = 0; q < 4; q++) {
            ull wv = dup2(w4[q]);
            accA[0] = fma2(*(const ull*)&xn_s[(c + q) * G1 + 0], wv, accA[0]);
            accA[1] = fma2(*(const ull*)&xn_s[(c + q) * G1 + 2], wv, accA[1]);
        }
    }
    float2 aA0 = unpk(accA[0]), aA1 = unpk(accA[1]);
    float ax[4] = {aA0.x, aA0.y, aA1.x, aA1.y};
    float bias = b1[o];
    float s1 = 0.f, s2 = 0.f;
    const float* wbase = g_w1t + o;          // [(c*11+t)*256 + o]

    for (int p = 0; p < 2; p++) {
        ull acc[J1];
#pragma unroll
        for (int j = 0; j < J1; j++) acc[j] = 0ull;

        for (int c = 0; c < DD; c++) {
            const float* wc = wbase + (size_t)c * T1 * O1;
            ull wd[T1];
#pragma unroll
            for (int t = 0; t < T1; t++) wd[t] = dup2(wc[t * O1]);  // coalesced LDG
            const float* ers = &ed_s[c * KK * G1];
            ull wnd[T1];
#pragma unroll
            for (int t = 0; t < T1; t++)
                wnd[t] = *(const ull*)&ers[t * G1 + 2 * p];
#pragma unroll
            for (int j = 0; j < J1; j++) {
#pragma unroll
                for (int t = 0; t < T1; t++)
                    acc[j] = fma2(wnd[(j + t) % T1], wd[t], acc[j]);
                if (j < J1 - 1)
                    wnd[j % T1] = *(const ull*)&ers[(j + T1) * G1 + 2 * p];
            }
        }
#pragma unroll
        for (int j = 0; j < J1; j++) {
            float2 v = unpk(acc[j]);
            float vx = v.x + ax[2 * p]     + bias;
            float vy = v.y + ax[2 * p + 1] + bias;
            g_h[((size_t)(b * NN + n0 + 2 * p)     * J1 + j) * O1 + o] = vx;
            g_h[((size_t)(b * NN + n0 + 2 * p + 1) * J1 + j) * O1 + o] = vy;
            s1 += vx + vy; s2 += vx * vx + vy * vy;
        }
    }
    g_p1[blockIdx.x * O1 + o] = s1;
    g_p2[blockIdx.x * O1 + o] = s2;
}

// ---------------- BN1 finalize ----------------
__global__ void k_bn1fin(const float* __restrict__ gamma, const float* __restrict__ beta) {
    int o = blockIdx.x;
    int tid = threadIdx.x;
    float s = 0.f, s2 = 0.f;
    for (int blk = tid; blk < NB1; blk += 256) {
        s  += g_p1[blk * O1 + o];
        s2 += g_p2[blk * O1 + o];
    }
    __shared__ float rs[256], rs2[256];
    rs[tid] = s; rs2[tid] = s2;
    __syncthreads();
    for (int t = 128; t > 0; t >>= 1) {
        if (tid < t) { rs[tid] += rs[tid + t]; rs2[tid] += rs2[tid + t]; }
        __syncthreads();
    }
    if (tid == 0) {
        float cnt  = (float)(BB * NN * J1);
        float mean = rs[0] / cnt;
        float var  = rs2[0] / cnt - mean * mean;
        float a    = gamma[o] * rsqrtf(var + 1e-5f);
        g_bn1a[o] = a;
        g_bn1b[o] = beta[o] - mean * a;
    }
}

// ---------------- conv2 fused, 3 blocks/SM, no xs smem ----------------
// smem = ed2[320*18] + hp2[640*18] = 17280 floats = 69.1KB
__global__ void __launch_bounds__(256, 3) k_conv2(const float* __restrict__ x,
                                                  const float* __restrict__ b2) {
    extern __shared__ float smem[];
    float* ed2 = smem;
    float* hp2 = smem + C2ED * RPAD;
    int b  = blockIdx.x / (NN / G2P);
    int n0 = (blockIdx.x % (NN / G2P)) * G2P;
    int tid = threadIdx.x;
    int o2 = tid;
    const float* xb = x + (size_t)b * DD * NN;

    ull acc[G2P / 2];
#pragma unroll
    for (int p = 0; p < G2P / 2; p++) acc[p] = 0ull;

    for (int pass = 0; pass < NCH; pass++) {
        if (pass > 0) __syncthreads();
        for (int i = tid; i < G2P * C2ED; i += 256) {
            int g = i / C2ED, m = i % C2ED;
            ed2[m * RPAD + g] = g_ed[(size_t)(b * NN + n0 + g) * (DD * KK) + pass * C2ED + m];
        }
        for (int i = tid; i < G2P * C2HP; i += 256) {
            int g = i / C2HP, r = i % C2HP;
            int j = r >> 6, oo = r & 63;
            int o = pass * 64 + oo;
            float raw = g_h[((size_t)(b * NN + n0 + g) * J1 + j) * O1 + o];
            float v = g_bn1a[o] * raw + g_bn1b[o];
            v = v > 0.f ? v : 0.01f * v;
            int cl = oo >> 1;
            int k  = (oo & 1) * J1 + j;
            hp2[(cl * KK + k) * RPAD + g] = v;
        }
        __syncthreads();

        if (pass == 0) {                   // A: constant-channel GEMV, broadcast LDG from x
            for (int c = 0; c < DD; c += 8) {
                float w8[8];
#pragma unroll
                for (int q = 0; q < 8; q++) w8[q] = g_w2a[(c + q) * O2C + o2];
#pragma unroll
                for (int q = 0; q < 8; q++) {
                    ull wv = dup2(w8[q]);
                    const float* xr = xb + (size_t)(c + q) * NN + n0;   // uniform row: broadcast
#pragma unroll
                    for (int p = 0; p < G2P / 2; p++)
                        acc[p] = fma2(*(const ull*)&xr[2 * p], wv, acc[p]);
                }
            }
        }
        for (int dcl = 0; dcl < 16; dcl++) {
            const float* wrow = &g_w2t[((pass * 16 + dcl) * KK) * O2C + o2];
            const float* er = &ed2[dcl * KK * RPAD];
#pragma unroll
            for (int sb = 0; sb < KK; sb += 10) {
                ull wd10[10];
#pragma unroll
                for (int q = 0; q < 10; q++) wd10[q] = dup2(wrow[(sb + q) * O2C]);
#pragma unroll
                for (int q = 0; q < 10; q++) {
                    const float* row = &er[(sb + q) * RPAD];
#pragma unroll
                    for (int p = 0; p < G2P / 2; p++)
                        acc[p] = fma2(*(const ull*)&row[2 * p], wd10[q], acc[p]);
                }
            }
        }
        for (int cl = 0; cl < 32; cl++) {
            const float* wrow = &g_w2c[((pass * 32 + cl) * KK) * O2C + o2];
            const float* hr = &hp2[cl * KK * RPAD];
#pragma unroll
            for (int sb = 0; sb < KK; sb += 10) {
                ull wd10[10];
#pragma unroll
                for (int q = 0; q < 10; q++) wd10[q] = dup2(wrow[(sb + q) * O2C]);
#pragma unroll
                for (int q = 0; q < 10; q++) {
                    const float* row = &hr[(sb + q) * RPAD];
#pragma unroll
                    for (int p = 0; p < G2P / 2; p++)
                        acc[p] = fma2(*(const ull*)&row[2 * p], wd10[q], acc[p]);
                }
            }
        }
    }

    float bias = b2[o2];
    float s1 = 0.f, s2 = 0.f;
#pragma unroll
    for (int p = 0; p < G2P / 2; p++) {
        float2 v = unpk(acc[p]);
        float yx = v.x + bias, yy = v.y + bias;
        g_y[(b * NN + n0 + 2 * p)     * O2C + o2] = yx;
        g_y[(b * NN + n0 + 2 * p + 1) * O2C + o2] = yy;
        s1 += yx + yy; s2 += yx * yx + yy * yy;
    }
    g_q1[blockIdx.x * O2C + o2] = s1;
    g_q2[blockIdx.x * O2C + o2] = s2;
}

// ---------------- BN2 finalize ----------------
__global__ void k_bn2fin(const float* __restrict__ gamma, const float* __restrict__ beta) {
    int o = blockIdx.x;
    int tid = threadIdx.x;
    float s = 0.f, s2 = 0.f;
    for (int blk = tid; blk < NB2; blk += 256) {
        s  += g_q1[blk * O2C + o];
        s2 += g_q2[blk * O2C + o];
    }
    __shared__ float rs[256], rs2[256];
    rs[tid] = s; rs2[tid] = s2;
    __syncthreads();
    for (int t = 128; t > 0; t >>= 1) {
        if (tid < t) { rs[tid] += rs[tid + t]; rs2[tid] += rs2[tid + t]; }
        __syncthreads();
    }
    if (tid == 0) {
        float cnt  = (float)(BB * NN);
        float mean = rs[0] / cnt;
        float var  = rs2[0] / cnt - mean * mean;
        float a    = gamma[o] * rsqrtf(var + 1e-5f);
        g_bn2a[o] = a;
        g_bn2b[o] = beta[o] - mean * a;
    }
}

// ---------------- output: tiled transpose ----------------
__global__ void __launch_bounds__(256) k_out(float* __restrict__ out) {
    __shared__ float sy[32 * 257];
    int b  = blockIdx.x >> 6;
    int n0 = (blockIdx.x & 63) * 32;
    int tid = threadIdx.x;

    for (int it = 0; it < 32; it++) {
        int g = it, o2 = tid;
        float v = g_y[(b * NN + n0 + g) * O2C + o2];
        v = g_bn2a[o2] * v + g_bn2b[o2];
        sy[g * 257 + o2] = v > 0.f ? v : 0.f;
    }
    __syncthreads();
    float* ob = out + (size_t)b * 524288;
    for (int it = 0; it < 32; it++) {
        int row = (tid >> 5) + it * 8;
        int g   = tid & 31;
        ob[(row >> 1) * 4096 + (row & 1) * 2048 + n0 + g] = sy[g * 257 + row];
    }
}

// ---------------- launch ----------------
extern "C" void kernel_launch(void* const* d_in, const int* in_sizes, int n_in,
                              void* d_out, int out_size) {
    const float* x   = (const float*)d_in[0];
    const float* w1  = (const float*)d_in[1];
    const float* b1  = (const float*)d_in[2];
    const float* g1  = (const float*)d_in[3];
    const float* be1 = (const float*)d_in[4];
    const float* w2  = (const float*)d_in[5];
    const float* b2  = (const float*)d_in[6];
    const float* g2  = (const float*)d_in[7];
    const float* be2 = (const float*)d_in[8];
    float* out = (float*)d_out;

    static int attr_done = 0;
    int smem1 = (DD * G1 + DD * KK * G1) * (int)sizeof(float);            // 21.5KB
    int smem2 = ((C2ED + C2HP) * RPAD) * (int)sizeof(float);              // 69.1KB
    if (!attr_done) {
        cudaFuncSetAttribute(k_conv1, cudaFuncAttributeMaxDynamicSharedMemorySize, smem1);
        cudaFuncSetAttribute(k_conv2, cudaFuncAttributeMaxDynamicSharedMemorySize, smem2);
        attr_done = 1;
    }

    // conv1 stays the 4th launch for ncu visibility
    k_tw1x<<<(O1 * CC * T1 + 255) / 256, 256>>>(w1);
    k_sq  <<<(BB * NN + 255) / 256, 256>>>(x);
    k_knn <<<BB * NN / GN, 256>>>(x);
    k_conv1<<<NB1, 256, smem1>>>(x, b1);
    k_tw2x<<<(O2C * CC * SS + 255) / 256, 256>>>(w2);
    k_bn1fin<<<O1, 256>>>(g1, be1);
    k_conv2<<<NB2, 256, smem2>>>(x, b2);
    k_bn2fin<<<O2C, 256>>>(g2, be2);
    k_out <<<BB * 64, 256>>>(out);
}

// round 16
// speedup vs baseline: 1.1074x; 1.0011x over previous
#include <cuda_runtime.h>
#include <math.h>
#include <stdint.h>

// Problem constants
#define BB   8
#define DD   64
#define NN   2048
#define KK   20
#define CC   128
#define O1   256
#define J1   10
#define T1   11
#define O2C  256
#define SS   40
#define GN   8       // points per knn block (warp-per-point selection)
#define G1   4
#define G2P  16
#define NCH  4
#define RPAD 18
#define NB1  (BB * NN / G1)
#define NB2  (BB * NN / G2P)
#define C2HP (32 * KK)
#define C2ED (16 * KK)

typedef unsigned long long ull;

__device__ __forceinline__ ull fma2(ull a, ull b, ull c) {
    ull d;
    asm("fma.rn.f32x2 %0, %1, %2, %3;" : "=l"(d) : "l"(a), "l"(b), "l"(c));
    return d;
}
__device__ __forceinline__ ull dup2(float v) {
    ull d; unsigned int u = __float_as_uint(v);
    asm("mov.b64 %0, {%1, %1};" : "=l"(d) : "r"(u));
    return d;
}
__device__ __forceinline__ float2 unpk(ull v) {
    float2 r;
    asm("mov.b64 {%0, %1}, %2;" : "=f"(r.x), "=f"(r.y) : "l"(v));
    return r;
}

// ---------------- scratch ----------------
__device__ float g_sq[BB * NN];
__device__ int   g_idx[BB * NN * KK];
__device__ float g_ed[(size_t)BB * NN * 64 * KK];
__device__ float g_h [(size_t)BB * NN * J1 * O1];   // [b][n][j][o]
__device__ float g_bn1a[O1];
__device__ float g_bn1b[O1];
__device__ float g_y [BB * NN * O2C];
__device__ float g_bn2a[O2C];
__device__ float g_bn2b[O2C];
__device__ float g_w1t[64 * T1 * O1];               // [c][t][o]
__device__ float g_w1a[64 * O1];
__device__ float g_w2t[64 * KK * O2C];              // pairs: [(dch*10+sp)*2*O2C + 2*o + par]
__device__ float g_w2c[CC * KK * O2C];              // pairs: [(c*10+sp)*2*O2C + 2*o + par]
__device__ float g_w2a[64 * O2C];
__device__ float g_p1[NB1 * O1];
__device__ float g_p2[NB1 * O1];
__device__ float g_q1[NB2 * O2C];
__device__ float g_q2[NB2 * O2C];

// ---------------- weight preprocessing ----------------
__global__ void k_tw1x(const float* __restrict__ w1) {
    int i = blockIdx.x * 256 + threadIdx.x;
    if (i < O1 * CC * T1) {
        int o = i / (CC * T1);
        int r = i % (CC * T1);
        int c = r / T1, t = r % T1;
        if (c >= DD) g_w1t[((c - DD) * T1 + t) * O1 + o] = w1[i];
    }
    if (i < DD * O1) {
        int c = i & 63, o = i >> 6;
        float s = 0.f;
#pragma unroll
        for (int t = 0; t < T1; t++) s += w1[(o * CC + c) * T1 + t];
        g_w1a[c * O1 + o] = s;
    }
}
__global__ void k_tw2x(const float* __restrict__ w2) {
    int i = blockIdx.x * 256 + threadIdx.x;
    if (i < O2C * CC * SS) {
        int o = i / (CC * SS);
        int r = i % (CC * SS);
        int c = r / SS, s = r % SS;
        if (s >= KK) {
            int k = s - KK;
            g_w2c[(c * 10 + (k >> 1)) * 2 * O2C + 2 * o + (k & 1)] = w2[i];
        } else if (c >= DD) {
            g_w2t[((c - DD) * 10 + (s >> 1)) * 2 * O2C + 2 * o + (s & 1)] = w2[i];
        }
    }
    if (i < DD * O2C) {
        int c = i & 63, o = i >> 6;
        float s = 0.f;
#pragma unroll
        for (int t = 0; t < KK; t++) s += w2[(o * CC + c) * SS + t];
        g_w2a[c * O2C + o] = s;
    }
}

// ---------------- squared norms (mul-then-add, matches ref) ----------
__global__ void k_sq(const float* __restrict__ x) {
    int i = blockIdx.x * 256 + threadIdx.x;
    if (i >= BB * NN) return;
    int b = i / NN, n = i % NN;
    const float* xb = x + (size_t)b * DD * NN + n;
    float s = 0.f;
#pragma unroll
    for (int d = 0; d < DD; d++) {
        float v = xb[(size_t)d * NN];
        s = __fadd_rn(s, __fmul_rn(v, v));
    }
    g_sq[i] = s;
}

// ---------------- kNN — GN=8, warp-per-point selection (no barriers) --------
// dyn smem: xn[8*64] + dist[8*2048] = 16896 floats = 67.6KB
__global__ void __launch_bounds__(256, 2) k_knn(const float* __restrict__ x) {
    extern __shared__ float ksm[];
    float* xn   = ksm;                 // [g*64 + d]
    float* dist = ksm + GN * DD;       // [g*2048 + m]
    int b  = blockIdx.x / (NN / GN);
    int n0 = (blockIdx.x % (NN / GN)) * GN;
    int tid = threadIdx.x;

    const float* xb = x + (size_t)b * DD * NN;
    for (int i = tid; i < GN * DD; i += 256) {
        int g = i / DD, d = i % DD;
        xn[i] = xb[(size_t)d * NN + n0 + g];
    }
    __syncthreads();

    float sqn[GN];
#pragma unroll
    for (int g = 0; g < GN; g++) sqn[g] = g_sq[b * NN + n0 + g];

    ull ddot[GN][4];
#pragma unroll
    for (int g = 0; g < GN; g++)
#pragma unroll
        for (int q = 0; q < 4; q++) ddot[g][q] = 0ull;

    for (int d = 0; d < DD; d++) {
        const ulonglong2* row2 = (const ulonglong2*)(xb + (size_t)d * NN);
        ulonglong2 A0 = row2[tid];          // m = 4tid..4tid+3
        ulonglong2 A1 = row2[tid + 256];    // m = 1024+4tid..+3
#pragma unroll
        for (int g = 0; g < GN; g++) {
            ull xn2 = dup2(xn[g * DD + d]);
            ddot[g][0] = fma2(A0.x, xn2, ddot[g][0]);
            ddot[g][1] = fma2(A0.y, xn2, ddot[g][1]);
            ddot[g][2] = fma2(A1.x, xn2, ddot[g][2]);
            ddot[g][3] = fma2(A1.y, xn2, ddot[g][3]);
        }
    }
#pragma unroll
    for (int q = 0; q < 4; q++) {
        int mbase = 4 * tid + (q & 1) * 2 + (q >> 1) * 1024;
        float sm0 = g_sq[b * NN + mbase];
        float sm1 = g_sq[b * NN + mbase + 1];
#pragma unroll
        for (int g = 0; g < GN; g++) {
            float2 dg = unpk(ddot[g][q]);
            float t0 = __fadd_rn(sqn[g], sm0);
            float d0 = __fsub_rn(t0, __fmul_rn(2.f, dg.x));
            dist[g * NN + mbase] = (mbase == n0 + g) ? 1e30f : d0;
            float t1 = __fadd_rn(sqn[g], sm1);
            float d1 = __fsub_rn(t1, __fmul_rn(2.f, dg.y));
            dist[g * NN + mbase + 1] = (mbase + 1 == n0 + g) ? 1e30f : d1;
        }
    }
    __syncthreads();

    // selection: warp g owns point g; lane scans m = lane + 32*r
    int g = tid >> 5;
    int lane = tid & 31;
    const int gbase = g * NN;

    float bv = 1e30f; int bi = 1 << 29;
#pragma unroll 8
    for (int r = 0; r < 64; r++) {
        int m = lane + 32 * r;
        float v = dist[gbase + m];
        if (v < bv || (v == bv && m < bi)) { bv = v; bi = m; }
    }
    for (int kk = 0; kk < KK; kk++) {
        float v = bv; int idx = bi;
#pragma unroll
        for (int s = 16; s; s >>= 1) {
            float vo = __shfl_xor_sync(0xffffffffu, v, s);
            int   io = __shfl_xor_sync(0xffffffffu, idx, s);
            if (vo < v || (vo == v && io < idx)) { v = vo; idx = io; }
        }
        if (lane == 0) g_idx[(b * NN + n0 + g) * KK + kk] = idx;
        if ((idx & 31) == lane) {              // owner removes + rescans its 64
            dist[gbase + idx] = 1e30f;
            bv = 1e30f; bi = 1 << 29;
#pragma unroll 8
            for (int r = 0; r < 64; r++) {
                int m = lane + 32 * r;
                float vv = dist[gbase + m];
                if (vv < bv || (vv == bv && m < bi)) { bv = vv; bi = m; }
            }
        }
    }
}

// ---------------- conv1: barrier-free, p-outer, 4 blocks/SM ----------------
// dyn smem: xn_s[256] + ed_s[5120] = 21.5KB
__global__ void __launch_bounds__(256, 4) k_conv1(const float* __restrict__ x,
                                                  const float* __restrict__ b1) {
    extern __shared__ float smem[];
    float* xn_s = smem;
    float* ed_s = smem + DD * G1;
    int b  = blockIdx.x / (NN / G1);
    int n0 = (blockIdx.x % (NN / G1)) * G1;
    int tid = threadIdx.x;
    const float* xb = x + (size_t)b * DD * NN;

    for (int i = tid; i < DD * G1; i += 256) {
        int c = i >> 2, g = i & 3;
        xn_s[i] = xb[(size_t)c * NN + n0 + g];
    }
    for (int i = tid; i < DD * KK * G1; i += 256) {
        int g = i & 3, m = i >> 2;
        int d = m / KK, k = m % KK;
        int n = n0 + g;
        int mm = g_idx[(b * NN + n) * KK + k];
        float v = xb[(size_t)d * NN + mm] - xb[(size_t)d * NN + n];
        ed_s[i] = v;
        g_ed[(size_t)(b * NN + n) * (DD * KK) + m] = v;
    }
    __syncthreads();

    int o = tid;
    ull accA[2] = {0ull, 0ull};
    for (int c = 0; c < DD; c += 4) {
        float w4[4];
#pragma unroll
        for (int q = 0; q < 4; q++) w4[q] = g_w1a[(c + q) * O1 + o];
#pragma unroll
        for (int q = 0; q < 4; q++) {
            ull wv = dup2(w4[q]);
            accA[0] = fma2(*(const ull*)&xn_s[(c + q) * G1 + 0], wv, accA[0]);
            accA[1] = fma2(*(const ull*)&xn_s[(c + q) * G1 + 2], wv, accA[1]);
        }
    }
    float2 aA0 = unpk(accA[0]), aA1 = unpk(accA[1]);
    float ax[4] = {aA0.x, aA0.y, aA1.x, aA1.y};
    float bias = b1[o];
    float s1 = 0.f, s2 = 0.f;
    const float* wbase = g_w1t + o;

    for (int p = 0; p < 2; p++) {
        ull acc[J1];
#pragma unroll
        for (int j = 0; j < J1; j++) acc[j] = 0ull;

        for (int c = 0; c < DD; c++) {
            const float* wc = wbase + (size_t)c * T1 * O1;
            ull wd[T1];
#pragma unroll
            for (int t = 0; t < T1; t++) wd[t] = dup2(wc[t * O1]);
            const float* ers = &ed_s[c * KK * G1];
            ull wnd[T1];
#pragma unroll
            for (int t = 0; t < T1; t++)
                wnd[t] = *(const ull*)&ers[t * G1 + 2 * p];
#pragma unroll
            for (int j = 0; j < J1; j++) {
#pragma unroll
                for (int t = 0; t < T1; t++)
                    acc[j] = fma2(wnd[(j + t) % T1], wd[t], acc[j]);
                if (j < J1 - 1)
                    wnd[j % T1] = *(const ull*)&ers[(j + T1) * G1 + 2 * p];
            }
        }
#pragma unroll
        for (int j = 0; j < J1; j++) {
            float2 v = unpk(acc[j]);
            float vx = v.x + ax[2 * p]     + bias;
            float vy = v.y + ax[2 * p + 1] + bias;
            g_h[((size_t)(b * NN + n0 + 2 * p)     * J1 + j) * O1 + o] = vx;
            g_h[((size_t)(b * NN + n0 + 2 * p + 1) * J1 + j) * O1 + o] = vy;
            s1 += vx + vy; s2 += vx * vx + vy * vy;
        }
    }
    g_p1[blockIdx.x * O1 + o] = s1;
    g_p2[blockIdx.x * O1 + o] = s2;
}

// ---------------- BN1 finalize ----------------
__global__ void k_bn1fin(const float* __restrict__ gamma, const float* __restrict__ beta) {
    int o = blockIdx.x;
    int tid = threadIdx.x;
    float s = 0.f, s2 = 0.f;
    for (int blk = tid; blk < NB1; blk += 256) {
        s  += g_p1[blk * O1 + o];
        s2 += g_p2[blk * O1 + o];
    }
    __shared__ float rs[256], rs2[256];
    rs[tid] = s; rs2[tid] = s2;
    __syncthreads();
    for (int t = 128; t > 0; t >>= 1) {
        if (tid < t) { rs[tid] += rs[tid + t]; rs2[tid] += rs2[tid + t]; }
        __syncthreads();
    }
    if (tid == 0) {
        float cnt  = (float)(BB * NN * J1);
        float mean = rs[0] / cnt;
        float var  = rs2[0] / cnt - mean * mean;
        float a    = gamma[o] * rsqrtf(var + 1e-5f);
        g_bn1a[o] = a;
        g_bn1b[o] = beta[o] - mean * a;
    }
}

// ---------------- conv2 fused, 3 blocks/SM, paired weight LDG.64 -------------
// smem = ed2[320*18] + hp2[640*18] = 17280 floats = 69.1KB
__global__ void __launch_bounds__(256, 3) k_conv2(const float* __restrict__ x,
                                                  const float* __restrict__ b2) {
    extern __shared__ float smem[];
    float* ed2 = smem;
    float* hp2 = smem + C2ED * RPAD;
    int b  = blockIdx.x / (NN / G2P);
    int n0 = (blockIdx.x % (NN / G2P)) * G2P;
    int tid = threadIdx.x;
    int o2 = tid;
    const float* xb = x + (size_t)b * DD * NN;

    ull acc[G2P / 2];
#pragma unroll
    for (int p = 0; p < G2P / 2; p++) acc[p] = 0ull;

    for (int pass = 0; pass < NCH; pass++) {
        if (pass > 0) __syncthreads();
        for (int i = tid; i < G2P * C2ED; i += 256) {
            int g = i / C2ED, m = i % C2ED;
            ed2[m * RPAD + g] = g_ed[(size_t)(b * NN + n0 + g) * (DD * KK) + pass * C2ED + m];
        }
        for (int i = tid; i < G2P * C2HP; i += 256) {
            int g = i / C2HP, r = i % C2HP;
            int j = r >> 6, oo = r & 63;
            int o = pass * 64 + oo;
            float raw = g_h[((size_t)(b * NN + n0 + g) * J1 + j) * O1 + o];
            float v = g_bn1a[o] * raw + g_bn1b[o];
            v = v > 0.f ? v : 0.01f * v;
            int cl = oo >> 1;
            int k  = (oo & 1) * J1 + j;
            hp2[(cl * KK + k) * RPAD + g] = v;
        }
        __syncthreads();

        if (pass == 0) {                   // A: constant-channel GEMV (broadcast LDG)
            for (int c = 0; c < DD; c += 8) {
                float w8[8];
#pragma unroll
                for (int q = 0; q < 8; q++) w8[q] = g_w2a[(c + q) * O2C + o2];
#pragma unroll
                for (int q = 0; q < 8; q++) {
                    ull wv = dup2(w8[q]);
                    const float* xr = xb + (size_t)(c + q) * NN + n0;
#pragma unroll
                    for (int p = 0; p < G2P / 2; p++)
                        acc[p] = fma2(*(const ull*)&xr[2 * p], wv, acc[p]);
                }
            }
        }
        // B: diff-channel ee conv (paired weights)
        for (int dcl = 0; dcl < 16; dcl++) {
            const float2* wp = (const float2*)g_w2t + ((pass * 16 + dcl) * 10) * O2C + o2;
            const float* er = &ed2[dcl * KK * RPAD];
#pragma unroll
            for (int sb = 0; sb < 2; sb++) {
                ull wd10[10];
#pragma unroll
                for (int qp = 0; qp < 5; qp++) {
                    float2 w = wp[(sb * 5 + qp) * O2C];
                    wd10[2 * qp]     = dup2(w.x);
                    wd10[2 * qp + 1] = dup2(w.y);
                }
#pragma unroll
                for (int q = 0; q < 10; q++) {
                    const float* row = &er[(sb * 10 + q) * RPAD];
#pragma unroll
                    for (int p = 0; p < G2P / 2; p++)
                        acc[p] = fma2(*(const ull*)&row[2 * p], wd10[q], acc[p]);
                }
            }
        }
        // C: inte (hp) conv (paired weights)
        for (int cl = 0; cl < 32; cl++) {
            const float2* wp = (const float2*)g_w2c + ((pass * 32 + cl) * 10) * O2C + o2;
            const float* hr = &hp2[cl * KK * RPAD];
#pragma unroll
            for (int sb = 0; sb < 2; sb++) {
                ull wd10[10];
#pragma unroll
                for (int qp = 0; qp < 5; qp++) {
                    float2 w = wp[(sb * 5 + qp) * O2C];
                    wd10[2 * qp]     = dup2(w.x);
                    wd10[2 * qp + 1] = dup2(w.y);
                }
#pragma unroll
                for (int q = 0; q < 10; q++) {
                    const float* row = &hr[(sb * 10 + q) * RPAD];
#pragma unroll
                    for (int p = 0; p < G2P / 2; p++)
                        acc[p] = fma2(*(const ull*)&row[2 * p], wd10[q], acc[p]);
                }
            }
        }
    }

    float bias = b2[o2];
    float s1 = 0.f, s2 = 0.f;
#pragma unroll
    for (int p = 0; p < G2P / 2; p++) {
        float2 v = unpk(acc[p]);
        float yx = v.x + bias, yy = v.y + bias;
        g_y[(b * NN + n0 + 2 * p)     * O2C + o2] = yx;
        g_y[(b * NN + n0 + 2 * p + 1) * O2C + o2] = yy;
        s1 += yx + yy; s2 += yx * yx + yy * yy;
    }
    g_q1[blockIdx.x * O2C + o2] = s1;
    g_q2[blockIdx.x * O2C + o2] = s2;
}

// ---------------- BN2 finalize ----------------
__global__ void k_bn2fin(const float* __restrict__ gamma, const float* __restrict__ beta) {
    int o = blockIdx.x;
    int tid = threadIdx.x;
    float s = 0.f, s2 = 0.f;
    for (int blk = tid; blk < NB2; blk += 256) {
        s  += g_q1[blk * O2C + o];
        s2 += g_q2[blk * O2C + o];
    }
    __shared__ float rs[256], rs2[256];
    rs[tid] = s; rs2[tid] = s2;
    __syncthreads();
    for (int t = 128; t > 0; t >>= 1) {
        if (tid < t) { rs[tid] += rs[tid + t]; rs2[tid] += rs2[tid + t]; }
        __syncthreads();
    }
    if (tid == 0) {
        float cnt  = (float)(BB * NN);
        float mean = rs[0] / cnt;
        float var  = rs2[0] / cnt - mean * mean;
        float a    = gamma[o] * rsqrtf(var + 1e-5f);
        g_bn2a[o] = a;
        g_bn2b[o] = beta[o] - mean * a;
    }
}

// ---------------- output: tiled transpose ----------------
__global__ void __launch_bounds__(256) k_out(float* __restrict__ out) {
    __shared__ float sy[32 * 257];
    int b  = blockIdx.x >> 6;
    int n0 = (blockIdx.x & 63) * 32;
    int tid = threadIdx.x;

    for (int it = 0; it < 32; it++) {
        int g = it, o2 = tid;
        float v = g_y[(b * NN + n0 + g) * O2C + o2];
        v = g_bn2a[o2] * v + g_bn2b[o2];
        sy[g * 257 + o2] = v > 0.f ? v : 0.f;
    }
    __syncthreads();
    float* ob = out + (size_t)b * 524288;
    for (int it = 0; it < 32; it++) {
        int row = (tid >> 5) + it * 8;
        int g   = tid & 31;
        ob[(row >> 1) * 4096 + (row & 1) * 2048 + n0 + g] = sy[g * 257 + row];
    }
}

// ---------------- launch ----------------
extern "C" void kernel_launch(void* const* d_in, const int* in_sizes, int n_in,
                              void* d_out, int out_size) {
    const float* x   = (const float*)d_in[0];
    const float* w1  = (const float*)d_in[1];
    const float* b1  = (const float*)d_in[2];
    const float* g1  = (const float*)d_in[3];
    const float* be1 = (const float*)d_in[4];
    const float* w2  = (const float*)d_in[5];
    const float* b2  = (const float*)d_in[6];
    const float* g2  = (const float*)d_in[7];
    const float* be2 = (const float*)d_in[8];
    float* out = (float*)d_out;

    static int attr_done = 0;
    int smemk = (GN * DD + GN * NN) * (int)sizeof(float);                 // 67.6KB
    int smem1 = (DD * G1 + DD * KK * G1) * (int)sizeof(float);            // 21.5KB
    int smem2 = ((C2ED + C2HP) * RPAD) * (int)sizeof(float);              // 69.1KB
    if (!attr_done) {
        cudaFuncSetAttribute(k_knn,   cudaFuncAttributeMaxDynamicSharedMemorySize, smemk);
        cudaFuncSetAttribute(k_conv1, cudaFuncAttributeMaxDynamicSharedMemorySize, smem1);
        cudaFuncSetAttribute(k_conv2, cudaFuncAttributeMaxDynamicSharedMemorySize, smem2);
        attr_done = 1;
    }

    // conv1 stays the 4th launch for ncu visibility
    k_tw1x<<<(O1 * CC * T1 + 255) / 256, 256>>>(w1);
    k_sq  <<<(BB * NN + 255) / 256, 256>>>(x);
    k_knn <<<BB * NN / GN, 256, smemk>>>(x);
    k_conv1<<<NB1, 256, smem1>>>(x, b1);
    k_tw2x<<<(O2C * CC * SS + 255) / 256, 256>>>(w2);
    k_bn1fin<<<O1, 256>>>(g1, be1);
    k_conv2<<<NB2, 256, smem2>>>(x, b2);
    k_bn2fin<<<O2C, 256>>>(g2, be2);
    k_out <<<BB * 64, 256>>>(out);
}